// round 11
// baseline (speedup 1.0000x reference)
#include <cuda_runtime.h>
#include <math.h>

#define Bsz   256
#define Tlen  1024
#define Hdim  128
#define NBLK  128      // 8 batch-tiles x 16 unit-tiles
#define NTHR  384      // 8 gemm warps + 4 helper warps
#define MT    32       // batches per CTA
#define UT    8        // hidden units per CTA (x4 gates = 32 rows)
#define AST   68       // a2f row stride in floats (padded for conflict-free groups)

// k2 (k-pair) bounds; slot map: 0=x, 1=zero, 2..129=h1, 130..257=h2, 258..385=h3
#define K2_1  65       // x+h1: k2 [0,65)
#define K2_2  129      // h2:   k2 [65,129)
#define K2_3  193      // h3:   k2 [129,193)

// ---- shared memory layout (float offsets) ----
#define OFF_W1 0
#define OFF_W2 (OFF_W1 + K2_1*64)       // 4160
#define OFF_W3 (OFF_W2 + K2_2*64)       // 12416
#define OFF_A  (OFF_W3 + K2_3*64)       // 24768  activations float2[k2][perm(m)], stride AST
#define OFF_G  (OFF_A  + K2_3*AST)      // 37892  gate partials: 8 x [32 rows][32 m]
#define OFF_C  (OFF_G  + 8*1024)        // 46084  c state [3][8][32]
#define OFF_BS (OFF_C  + 768)           // 46852  combined biases [3][32]
#define OFF_WL (OFF_BS + 96)            // 46948  W_lin slot space [388]
#define OFF_OP (OFF_WL + 388)           // 47336  o partials [8][32]
#define OFF_BL (OFF_OP + 256)           // 47592  b_lin
#define SMEM_FLOATS (OFF_BL + 4)        // 47596
#define SMEM_BYTES  (SMEM_FLOATS*4)     // 190384 bytes -> 1 CTA/SM

// ---- global scratch ----
__device__ __align__(256) float g_h[3][Hdim][Bsz];   // [layer][unit][batch]
__device__ unsigned g_flag[8][3][16][32];            // one 128B line per flag

__device__ __forceinline__ unsigned ld_acq(const unsigned* p) {
    unsigned v;
    asm volatile("ld.acquire.gpu.u32 %0, [%1];" : "=r"(v) : "l"(p) : "memory");
    return v;
}
__device__ __forceinline__ unsigned ld_rlx(const unsigned* p) {
    unsigned v;
    asm volatile("ld.relaxed.gpu.u32 %0, [%1];" : "=r"(v) : "l"(p) : "memory");
    return v;
}
__device__ __forceinline__ void st_rel(unsigned* p, unsigned v) {
    asm volatile("st.release.gpu.u32 [%0], %1;" :: "l"(p), "r"(v) : "memory");
}
__device__ __forceinline__ void fence_acq() {
    asm volatile("fence.acq_rel.gpu;" ::: "memory");
}

#define FMA2(d,a,b) asm("fma.rn.f32x2 %0, %1, %2, %0;" : "+l"(d) : "l"(a), "l"(b))

// permuted batch position within an a2f row (bank-conflict-free batch groups)
__device__ __forceinline__ int posf(int m)  { return 2*m + (m >= 16 ? 4 : 0); }
__device__ __forceinline__ int pos4(int bg) { return 8*bg + (bg >= 4 ? 4 : 0); }

// 32rows x 32batch GEMM, one warp per k2 in [lo,hi).
// Lane (rg=lane>>3, bg=lane&7) owns rows 8rg..8rg+7 x batches 4bg..4bg+3.
// acc[q*4+i]: f32x2 (even-k, odd-k) partial for (row 8rg+q, batch 4bg+i).
__device__ __forceinline__ void gemm8x4(const float* __restrict__ wb,
                                        const float* __restrict__ a2f,
                                        int rg16, int apos, int lo, int hi,
                                        unsigned long long* __restrict__ acc)
{
#pragma unroll 2
    for (int k2 = lo; k2 < hi; k2++) {
        const float* wp = wb + k2*64 + rg16;
        const float* ap = a2f + k2*AST + apos;
        ulonglong2 wA = *(const ulonglong2*)(wp);        // rows q0,q1
        ulonglong2 wB = *(const ulonglong2*)(wp + 4);    // q2,q3
        ulonglong2 wC = *(const ulonglong2*)(wp + 8);    // q4,q5
        ulonglong2 wD = *(const ulonglong2*)(wp + 12);   // q6,q7
        ulonglong2 aA = *(const ulonglong2*)(ap);        // batches i0,i1
        ulonglong2 aB = *(const ulonglong2*)(ap + 4);    // i2,i3
        FMA2(acc[ 0], aA.x, wA.x); FMA2(acc[ 1], aA.y, wA.x); FMA2(acc[ 2], aB.x, wA.x); FMA2(acc[ 3], aB.y, wA.x);
        FMA2(acc[ 4], aA.x, wA.y); FMA2(acc[ 5], aA.y, wA.y); FMA2(acc[ 6], aB.x, wA.y); FMA2(acc[ 7], aB.y, wA.y);
        FMA2(acc[ 8], aA.x, wB.x); FMA2(acc[ 9], aA.y, wB.x); FMA2(acc[10], aB.x, wB.x); FMA2(acc[11], aB.y, wB.x);
        FMA2(acc[12], aA.x, wB.y); FMA2(acc[13], aA.y, wB.y); FMA2(acc[14], aB.x, wB.y); FMA2(acc[15], aB.y, wB.y);
        FMA2(acc[16], aA.x, wC.x); FMA2(acc[17], aA.y, wC.x); FMA2(acc[18], aB.x, wC.x); FMA2(acc[19], aB.y, wC.x);
        FMA2(acc[20], aA.x, wC.y); FMA2(acc[21], aA.y, wC.y); FMA2(acc[22], aB.x, wC.y); FMA2(acc[23], aB.y, wC.y);
        FMA2(acc[24], aA.x, wD.x); FMA2(acc[25], aA.y, wD.x); FMA2(acc[26], aB.x, wD.x); FMA2(acc[27], aB.y, wD.x);
        FMA2(acc[28], aA.x, wD.y); FMA2(acc[29], aA.y, wD.y); FMA2(acc[30], aB.x, wD.y); FMA2(acc[31], aB.y, wD.y);
    }
}

// fold f32x2 halves, STS.128 per row (4 consecutive batches)
__device__ __forceinline__ void store_gates(float* __restrict__ gsh, int wi,
                                            int rg, int bg,
                                            const unsigned long long* __restrict__ acc)
{
    float* gp = gsh + wi*1024 + (8*rg)*32 + 4*bg;
#pragma unroll
    for (int q = 0; q < 8; q++) {
        float4 v; float lo, hi;
        asm("mov.b64 {%0, %1}, %2;" : "=f"(lo), "=f"(hi) : "l"(acc[q*4+0])); v.x = lo + hi;
        asm("mov.b64 {%0, %1}, %2;" : "=f"(lo), "=f"(hi) : "l"(acc[q*4+1])); v.y = lo + hi;
        asm("mov.b64 {%0, %1}, %2;" : "=f"(lo), "=f"(hi) : "l"(acc[q*4+2])); v.z = lo + hi;
        asm("mov.b64 {%0, %1}, %2;" : "=f"(lo), "=f"(hi) : "l"(acc[q*4+3])); v.w = lo + hi;
        *(float4*)(gp + q*32) = v;
    }
}

__device__ __forceinline__ float sigm(float v) {
    return __fdividef(1.f, 1.f + __expf(-v));
}
__device__ __forceinline__ float tanh_fast(float v) {
    return 1.f - __fdividef(2.f, __expf(2.f*v) + 1.f);
}

// combine 8 k-octant partials + bias, update c (SMEM), write h to global L2
__device__ __forceinline__ void cell_update(int layer, int u, int m, int nt, int m0,
                                            const float* __restrict__ gsh,
                                            const float* __restrict__ bs,
                                            float* __restrict__ csh,
                                            float* __restrict__ hglob)
{
    float xi = bs[ 0 + u], xf = bs[ 8 + u], xg = bs[16 + u], xo = bs[24 + u];
#pragma unroll
    for (int p = 0; p < 8; p++) {
        const float* gp = gsh + p*1024 + m;
        xi += gp[( 0 + u)*32];
        xf += gp[( 8 + u)*32];
        xg += gp[(16 + u)*32];
        xo += gp[(24 + u)*32];
    }
    float ii = sigm(xi);
    float ff = sigm(xf);
    float gg = tanh_fast(xg);
    float oo = sigm(xo);
    float* cp = csh + layer*(UT*32) + u*32 + m;
    float c = ff * cp[0] + ii * gg;
    cp[0] = c;
    hglob[(nt*UT + u)*Bsz + m0 + m] = oo * tanh_fast(c);
}

// helper warps: sweep-poll 4 producers' flags (relaxed, pipelined), one acquire
// fence, then pull each producer's 8x32 h slice into a2f as packed float2.
__device__ __forceinline__ void helper_refresh(int mt, int ph, unsigned tok, int h, int lane,
                                               const float* __restrict__ hg,
                                               float* __restrict__ a2f, int sbase, int m0)
{
    const unsigned* f0 = &g_flag[mt][ph][4*h + 0][0];
    const unsigned* f1 = &g_flag[mt][ph][4*h + 1][0];
    const unsigned* f2 = &g_flag[mt][ph][4*h + 2][0];
    const unsigned* f3 = &g_flag[mt][ph][4*h + 3][0];
    unsigned ok = 0;
    while (ok != 0xFu) {
        if (!(ok & 1u) && (int)(ld_rlx(f0) - tok) >= 0) ok |= 1u;
        if (!(ok & 2u) && (int)(ld_rlx(f1) - tok) >= 0) ok |= 2u;
        if (!(ok & 4u) && (int)(ld_rlx(f2) - tok) >= 0) ok |= 4u;
        if (!(ok & 8u) && (int)(ld_rlx(f3) - tok) >= 0) ok |= 8u;
    }
    fence_acq();
    const int pf = posf(lane);
#pragma unroll
    for (int j = 0; j < 4; j++) {
        int p = 4*h + j;
        const float* hp = hg + (p*8)*Bsz + m0 + lane;
#pragma unroll
        for (int up = 0; up < 4; up++) {
            float v0 = __ldcg(hp + (2*up    )*Bsz);
            float v1 = __ldcg(hp + (2*up + 1)*Bsz);
            int srow = ((sbase + 8*p) >> 1) + up;     // (sbase+8p+2up)/2
            *(float2*)(a2f + srow*AST + pf) = make_float2(v0, v1);
        }
    }
}

__global__ void __launch_bounds__(NTHR, 1)
lstm_forecast_kernel(const float* __restrict__ x,
                     const float* __restrict__ Wih1, const float* __restrict__ Whh1,
                     const float* __restrict__ bih1, const float* __restrict__ bhh1,
                     const float* __restrict__ Wih2, const float* __restrict__ Whh2,
                     const float* __restrict__ bih2, const float* __restrict__ bhh2,
                     const float* __restrict__ Wih3, const float* __restrict__ Whh3,
                     const float* __restrict__ bih3, const float* __restrict__ bhh3,
                     const float* __restrict__ Wlin, const float* __restrict__ blin,
                     float* __restrict__ out, int fut)
{
    extern __shared__ float sm[];
    const int tid  = threadIdx.x;
    const int lane = tid & 31;
    const int wi   = tid >> 5;          // 0..7 gemm, 8..11 helper
    const int rg   = lane >> 3;         // rows 8rg..8rg+7
    const int bg   = lane & 7;          // batches 4bg..4bg+3
    const int mt   = blockIdx.x >> 4;   // batch tile 0..7
    const int nt   = blockIdx.x & 15;   // unit tile 0..15
    const int m0   = mt * MT;

    float* w1  = sm + OFF_W1;
    float* w2p = sm + OFF_W2;
    float* w3p = sm + OFF_W3;
    float* a2f = sm + OFF_A;
    float* gsh = sm + OFF_G;
    float* csh = sm + OFF_C;
    float* bsh = sm + OFF_BS;
    float* wls = sm + OFF_WL;
    float* ops = sm + OFF_OP;

    // ---------------- prologue: pack weight slices [k2][r*2+j] ----------------
    for (int idx = tid; idx < K2_1*64; idx += NTHR) {
        int k2 = idx >> 6, rj = idx & 63, r = rj >> 1, j = rj & 1, s = 2*k2 + j;
        int rG = ((r >> 3) << 7) + nt*UT + (r & 7);
        w1[idx] = (s == 1) ? 0.f : ((s == 0) ? Wih1[rG] : Whh1[rG*Hdim + (s - 2)]);
    }
    for (int idx = tid; idx < K2_2*64; idx += NTHR) {
        int k2 = idx >> 6, rj = idx & 63, r = rj >> 1, j = rj & 1, s = 2*k2 + j;
        int rG = ((r >> 3) << 7) + nt*UT + (r & 7);
        float v;
        if (s == 1)        v = 0.f;
        else if (s == 0)   v = Wih2[rG*129];
        else if (s < 130)  v = Wih2[rG*129 + (s - 1)];
        else               v = Whh2[rG*Hdim + (s - 130)];
        w2p[idx] = v;
    }
    for (int idx = tid; idx < K2_3*64; idx += NTHR) {
        int k2 = idx >> 6, rj = idx & 63, r = rj >> 1, j = rj & 1, s = 2*k2 + j;
        int rG = ((r >> 3) << 7) + nt*UT + (r & 7);
        float v;
        if (s == 1)        v = 0.f;
        else if (s == 0)   v = Wih3[rG*257];
        else if (s < 258)  v = Wih3[rG*257 + (s - 1)];
        else               v = Whh3[rG*Hdim + (s - 258)];
        w3p[idx] = v;
    }
    if (tid < 32) {
        int r = tid;
        int rG = ((r >> 3) << 7) + nt*UT + (r & 7);
        bsh[0*32 + r] = bih1[rG] + bhh1[rG];
        bsh[1*32 + r] = bih2[rG] + bhh2[rG];
        bsh[2*32 + r] = bih3[rG] + bhh3[rG];
    }
    for (int s = tid; s < 388; s += NTHR)
        wls[s] = (s >= 386 || s == 1) ? 0.f : ((s == 0) ? Wlin[0] : Wlin[s - 1]);
    if (tid == 0) sm[OFF_BL] = blin[0];
    for (int idx = tid; idx < K2_3*AST; idx += NTHR) a2f[idx] = 0.f;  // h(-1)=0, pads=0
    for (int idx = tid; idx < 3*UT*32; idx += NTHR) csh[idx] = 0.f;

    const unsigned base = ld_acq(&g_flag[mt][0][nt][0]);   // replay-safe token base
    __syncthreads();

    const int Ttot = Tlen + fut;
    const int u = wi;        // cell-update mapping for wi<8 (unit = warp, batch = lane)
    const int m = lane;
    const float blv = sm[OFF_BL];
    const int rg16 = 16*rg;
    const int apos = pos4(bg);
    const int pf   = posf(lane);

    // per-warp k2 eighths (wi<8)
    const int xlo = (K2_1*wi) >> 3, xhi = (K2_1*(wi+1)) >> 3;   // x+h1 [0,65)
    const int r2lo = K2_1 + 8*wi, r2hi = r2lo + 8;              // h2   [65,129)
    const int r3lo = K2_2 + 8*wi, r3hi = r3lo + 8;              // h3   [129,193)

    const ulonglong1* wl2 = (const ulonglong1*)wls;             // f32x2 view of W_lin

    float xv = 0.f;
    if (tid < 32) xv = x[(m0 + tid)*Tlen + 0];

    for (int t = 0; t < Ttot; t++) {
        const unsigned tok0 = base + 3u*(unsigned)t + 1u;
        const unsigned tok1 = tok0 + 1u;
        const unsigned tok2 = tok0 + 2u;

        if (t < Tlen && tid < 32) *(float2*)(a2f + pf) = make_float2(xv, 0.f);  // k2=0: (x, 0)
        if (tid < 32 && t + 1 < Tlen) xv = x[(m0 + tid)*Tlen + (t + 1)];
        __syncthreads();                                        // S0

        // ---------- layer 1 (x + h1(t-1): local) ----------
        if (wi < 8) {
            unsigned long long acc[32];
#pragma unroll
            for (int q = 0; q < 32; q++) acc[q] = 0ull;
            gemm8x4(w1, a2f, rg16, apos, xlo, xhi, acc);
            store_gates(gsh, wi, rg, bg, acc);
        }
        __syncthreads();                                        // S1
        if (wi < 8) cell_update(0, u, m, nt, m0, gsh, bsh + 0, csh, &g_h[0][0][0]);
        __syncthreads();                                        // S2
        if (tid == 0) st_rel(&g_flag[mt][0][nt][0], tok0);

        // window0: acc2 r2-eighth on stale h2(t-1)  ||  helpers refresh h1(t)->slots 2..129
        unsigned long long acc2[32];
        if (wi < 8) {
#pragma unroll
            for (int q = 0; q < 32; q++) acc2[q] = 0ull;
            gemm8x4(w2p, a2f, rg16, apos, r2lo, r2hi, acc2);
        } else {
            helper_refresh(mt, 0, tok0, wi - 8, lane, &g_h[0][0][0], a2f, 2, m0);
        }
        __syncthreads();                                        // S3

        // ---------- layer 2 finish (x + fresh h1) ----------
        if (wi < 8) {
            gemm8x4(w2p, a2f, rg16, apos, xlo, xhi, acc2);
            store_gates(gsh, wi, rg, bg, acc2);
        }
        __syncthreads();                                        // S4
        if (wi < 8) cell_update(1, u, m, nt, m0, gsh, bsh + 32, csh, &g_h[1][0][0]);
        __syncthreads();                                        // S5
        if (tid == 0) st_rel(&g_flag[mt][1][nt][0], tok1);

        // window1: acc3 r3-eighth (stale h3 = correct) + x/h1-eighth  ||  refresh h2(t)
        unsigned long long acc3[32];
        if (wi < 8) {
#pragma unroll
            for (int q = 0; q < 32; q++) acc3[q] = 0ull;
            gemm8x4(w3p, a2f, rg16, apos, r3lo, r3hi, acc3);
            gemm8x4(w3p, a2f, rg16, apos, xlo, xhi, acc3);
        } else {
            helper_refresh(mt, 1, tok1, wi - 8, lane, &g_h[1][0][0], a2f, 130, m0);
        }
        __syncthreads();                                        // S6

        // ---------- layer 3 finish (fresh h2) ----------
        if (wi < 8) {
            gemm8x4(w3p, a2f, rg16, apos, r2lo, r2hi, acc3);
            store_gates(gsh, wi, rg, bg, acc3);
        }
        __syncthreads();                                        // S7
        if (wi < 8) cell_update(2, u, m, nt, m0, gsh, bsh + 64, csh, &g_h[2][0][0]);
        __syncthreads();                                        // S8
        if (tid == 0) st_rel(&g_flag[mt][2][nt][0], tok2);

        // window2: head over fresh x,h1,h2 (k2<129)  ||  refresh h3(t)->slots 258..385
        const bool doo = (nt == 0) || (t >= Tlen - 1);
        unsigned long long pacc = 0;
        if (wi < 8) {
            if (doo) {
                for (int k2 = wi; k2 < 129; k2 += 8) {
                    unsigned long long av = *(const unsigned long long*)(a2f + k2*AST + pf);
                    FMA2(pacc, av, wl2[k2].x);
                }
            }
        } else {
            helper_refresh(mt, 2, tok2, wi - 8, lane, &g_h[2][0][0], a2f, 258, m0);
        }
        __syncthreads();                                        // S9

        if (doo) {
            if (wi < 8) {
                for (int k2 = 129 + wi; k2 < 193; k2 += 8) {
                    unsigned long long av = *(const unsigned long long*)(a2f + k2*AST + pf);
                    FMA2(pacc, av, wl2[k2].x);
                }
                float plo, phi;
                asm("mov.b64 {%0, %1}, %2;" : "=f"(plo), "=f"(phi) : "l"(pacc));
                ops[wi*32 + lane] = plo + phi;
            }
            __syncthreads();                                    // S10
            if (wi == 0) {
                float o = blv;
#pragma unroll
                for (int j = 0; j < 8; j++) o += ops[j*32 + lane];
                if (nt == 0) out[(m0 + lane)*Ttot + t] = o;
                if (t >= Tlen - 1) a2f[pf] = o;    // feed back as next x (slot 0)
            }
        }
        // loop-top __syncthreads orders feedback write before next step's GEMM
    }
}

extern "C" void kernel_launch(void* const* d_in, const int* in_sizes, int n_in,
                              void* d_out, int out_size)
{
    const float* x    = (const float*)d_in[0];
    const float* Wih1 = (const float*)d_in[1];
    const float* Whh1 = (const float*)d_in[2];
    const float* bih1 = (const float*)d_in[3];
    const float* bhh1 = (const float*)d_in[4];
    const float* Wih2 = (const float*)d_in[5];
    const float* Whh2 = (const float*)d_in[6];
    const float* bih2 = (const float*)d_in[7];
    const float* bhh2 = (const float*)d_in[8];
    const float* Wih3 = (const float*)d_in[9];
    const float* Whh3 = (const float*)d_in[10];
    const float* bih3 = (const float*)d_in[11];
    const float* bhh3 = (const float*)d_in[12];
    const float* Wlin = (const float*)d_in[13];
    const float* blin = (const float*)d_in[14];
    (void)in_sizes; (void)n_in;

    int fut = out_size / Bsz - Tlen;

    cudaFuncSetAttribute((const void*)lstm_forecast_kernel,
                         cudaFuncAttributeMaxDynamicSharedMemorySize, SMEM_BYTES);

    lstm_forecast_kernel<<<NBLK, NTHR, SMEM_BYTES>>>(
        x, Wih1, Whh1, bih1, bhh1, Wih2, Whh2, bih2, bhh2,
        Wih3, Whh3, bih3, bhh3, Wlin, blin, (float*)d_out, fut);
}

// round 14
// speedup vs baseline: 1.0876x; 1.0876x over previous
#include <cuda_runtime.h>
#include <math.h>

#define Bsz   256
#define Tlen  1024
#define Hdim  128
#define NBLK  256      // 8 batch-tiles x 32 unit-tiles  (2 CTAs/SM)
#define NTHR  256
#define MT    32       // batches per CTA
#define UT    4        // hidden units per CTA (x4 gates = 16 rows)
#define NNT   32       // unit tiles
#define ASTR  386      // activation row stride (even; ASTR/2 odd -> conflict-free LDS.64)

// k2 (k-pair) bounds; slot map: 0=x, 1=zero, 2..129=h1, 130..257=h2, 258..385=h3
#define K2_1  65       // x+h1 part: k2 [0,65)
#define K2_2  129      // + h2 part: k2 [65,129)
#define K2_3  193      // + h3 part: k2 [129,193)

// ---- shared memory layout (float offsets); 16 rows/CTA => 32 floats per k2 ----
#define OFF_W1 0
#define OFF_W2 (OFF_W1 + K2_1*32)       // 2080
#define OFF_W3 (OFF_W2 + K2_2*32)       // 6208
#define OFF_A  (OFF_W3 + K2_3*32)       // 12384  activations [m][slot], stride ASTR
#define OFF_G  (OFF_A  + 32*ASTR)       // 24736  gate partials: 4 x [16 rows][32 m]
#define OFF_C  (OFF_G  + 4*512)         // 26784  c state [3][4][32]
#define OFF_BS (OFF_C  + 384)           // 27168  combined biases [3][16]
#define OFF_WL (OFF_BS + 48)            // 27216  W_lin in slot space [388]
#define OFF_OP (OFF_WL + 388)           // 27604  o partials [8][32]
#define OFF_BL (OFF_OP + 256)           // 27860  b_lin
#define SMEM_FLOATS (OFF_BL + 4)        // 27864
#define SMEM_BYTES  (SMEM_FLOATS*4)     // 111456 bytes -> 2 CTAs/SM

// ---- global scratch ----
__device__ __align__(256) float g_h[3][Hdim][Bsz];   // [layer][unit][batch]
__device__ unsigned g_flag[8][3][NNT][32];           // one 128B line per flag

__device__ __forceinline__ unsigned ld_acq(const unsigned* p) {
    unsigned v;
    asm volatile("ld.acquire.gpu.u32 %0, [%1];" : "=r"(v) : "l"(p) : "memory");
    return v;
}
__device__ __forceinline__ void st_rel(unsigned* p, unsigned v) {
    asm volatile("st.release.gpu.u32 [%0], %1;" :: "l"(p), "r"(v) : "memory");
}

#define FMA2(d,a,b) asm("fma.rn.f32x2 %0, %1, %2, %0;" : "+l"(d) : "l"(a), "l"(b))

// 8-row x 32-batch x [lo,hi) k2 GEMM. Warp rg2 owns rows 8*rg2..8*rg2+7.
// acc[q] is f32x2 (even-k, odd-k partial) for row 8*rg2+q.
__device__ __forceinline__ void gemm8(const float* __restrict__ wb,
                                      const float* __restrict__ arow,
                                      int rg2, int lo, int hi,
                                      unsigned long long* __restrict__ acc)
{
    const char* wp = (const char*)(wb + rg2*16);
#pragma unroll 2
    for (int k2 = lo; k2 < hi; k2++) {
        unsigned long long ap = *(const unsigned long long*)(arow + 2*k2);
        const ulonglong2* w = (const ulonglong2*)(wp + (size_t)k2*128);
        ulonglong2 w0 = w[0];
        ulonglong2 w1 = w[1];
        ulonglong2 w2 = w[2];
        ulonglong2 w3 = w[3];
        FMA2(acc[0], ap, w0.x);
        FMA2(acc[1], ap, w0.y);
        FMA2(acc[2], ap, w1.x);
        FMA2(acc[3], ap, w1.y);
        FMA2(acc[4], ap, w2.x);
        FMA2(acc[5], ap, w2.y);
        FMA2(acc[6], ap, w3.x);
        FMA2(acc[7], ap, w3.y);
    }
}

__device__ __forceinline__ void store_gates8(float* __restrict__ gsh, int kq, int rg2, int lane,
                                             const unsigned long long* __restrict__ acc)
{
    float* gp = gsh + kq*512 + (rg2*8)*32 + lane;
#pragma unroll
    for (int q = 0; q < 8; q++) {
        float lo, hi;
        asm("mov.b64 {%0, %1}, %2;" : "=f"(lo), "=f"(hi) : "l"(acc[q]));
        gp[q*32] = lo + hi;
    }
}

__device__ __forceinline__ float sigm(float v) {
    return __fdividef(1.f, 1.f + __expf(-v));
}
__device__ __forceinline__ float tanh_fast(float v) {
    return 1.f - __fdividef(2.f, __expf(2.f*v) + 1.f);
}

// combine 4 split-k partials + bias, update c (SMEM), write h to global L2.
// 16 rows: gate g rows g*4+u, u in [0,4). Only warps 0..3 call this (u = wi).
__device__ __forceinline__ void cell_update(int layer, int u, int m, int nt, int m0,
                                            const float* __restrict__ gsh,
                                            const float* __restrict__ bs,
                                            float* __restrict__ csh,
                                            float* __restrict__ hglob)
{
#define GSUM(r) (gsh[(r)*32+m] + gsh[512+(r)*32+m] + gsh[1024+(r)*32+m] + gsh[1536+(r)*32+m])
    float xi = GSUM( 0 + u) + bs[ 0 + u];
    float xf = GSUM( 4 + u) + bs[ 4 + u];
    float xg = GSUM( 8 + u) + bs[ 8 + u];
    float xo = GSUM(12 + u) + bs[12 + u];
#undef GSUM
    float ii = sigm(xi);
    float ff = sigm(xf);
    float gg = tanh_fast(xg);
    float oo = sigm(xo);
    float* cp = csh + layer*(UT*32) + u*32 + m;
    float c = ff * cp[0] + ii * gg;
    cp[0] = c;
    hglob[(nt*UT + u)*Bsz + m0 + m] = oo * tanh_fast(c);
}

// fused spin + refresh: warp wi waits for producers {4wi..4wi+3} (acquire spin
// per producer, R9-style) and pulls each 4-unit x 32-batch h slice into ash.
__device__ __forceinline__ void wait_refresh(int mt, int ph, unsigned tok, int wi, int lane,
                                             const float* __restrict__ hg,
                                             float* __restrict__ ash, int sbase, int m0)
{
    const int u  = lane >> 3;          // 0..3
    const int b4 = (lane & 7) * 4;     // 0..28
#pragma unroll
    for (int j = 0; j < 4; j++) {
        int p = 4*wi + j;
        const unsigned* fp = &g_flag[mt][ph][p][0];
        unsigned v;
        do { v = ld_acq(fp); } while ((int)(v - tok) < 0);
        float4 hv = __ldcg((const float4*)(hg + (p*UT + u)*Bsz + m0 + b4));
        float* dst = ash + sbase + p*UT + u;
        dst[(b4+0)*ASTR] = hv.x;
        dst[(b4+1)*ASTR] = hv.y;
        dst[(b4+2)*ASTR] = hv.z;
        dst[(b4+3)*ASTR] = hv.w;
    }
}

__global__ void __launch_bounds__(NTHR, 2)
lstm_forecast_kernel(const float* __restrict__ x,
                     const float* __restrict__ Wih1, const float* __restrict__ Whh1,
                     const float* __restrict__ bih1, const float* __restrict__ bhh1,
                     const float* __restrict__ Wih2, const float* __restrict__ Whh2,
                     const float* __restrict__ bih2, const float* __restrict__ bhh2,
                     const float* __restrict__ Wih3, const float* __restrict__ Whh3,
                     const float* __restrict__ bih3, const float* __restrict__ bhh3,
                     const float* __restrict__ Wlin, const float* __restrict__ blin,
                     float* __restrict__ out, int fut)
{
    extern __shared__ float sm[];
    const int tid  = threadIdx.x;
    const int lane = tid & 31;
    const int wi   = tid >> 5;
    const int rg2  = wi & 1;            // row group: rows 8*rg2 .. +7
    const int kq   = wi >> 1;           // k-quarter 0..3
    const int mt   = blockIdx.x >> 5;   // batch tile 0..7
    const int nt   = blockIdx.x & 31;   // unit tile 0..31
    const int m0   = mt * MT;

    float* w1  = sm + OFF_W1;
    float* w2p = sm + OFF_W2;
    float* w3p = sm + OFF_W3;
    float* ash = sm + OFF_A;
    float* gsh = sm + OFF_G;
    float* csh = sm + OFF_C;
    float* bsh = sm + OFF_BS;
    float* wls = sm + OFF_WL;
    float* ops = sm + OFF_OP;

    // ---------------- prologue: pack weight slices [k2][r*2+j], 16 rows ----------------
    // row r: gate = r>>2, unit = r&3 -> global row rG = (r>>2)*128 + nt*4 + (r&3)
    for (int idx = tid; idx < K2_1*32; idx += NTHR) {
        int k2 = idx >> 5, rj = idx & 31, r = rj >> 1, j = rj & 1, s = 2*k2 + j;
        int rG = ((r >> 2) << 7) + nt*UT + (r & 3);
        w1[idx] = (s == 1) ? 0.f : ((s == 0) ? Wih1[rG] : Whh1[rG*Hdim + (s - 2)]);
    }
    for (int idx = tid; idx < K2_2*32; idx += NTHR) {
        int k2 = idx >> 5, rj = idx & 31, r = rj >> 1, j = rj & 1, s = 2*k2 + j;
        int rG = ((r >> 2) << 7) + nt*UT + (r & 3);
        float v;
        if (s == 1)        v = 0.f;
        else if (s == 0)   v = Wih2[rG*129];
        else if (s < 130)  v = Wih2[rG*129 + (s - 1)];
        else               v = Whh2[rG*Hdim + (s - 130)];
        w2p[idx] = v;
    }
    for (int idx = tid; idx < K2_3*32; idx += NTHR) {
        int k2 = idx >> 5, rj = idx & 31, r = rj >> 1, j = rj & 1, s = 2*k2 + j;
        int rG = ((r >> 2) << 7) + nt*UT + (r & 3);
        float v;
        if (s == 1)        v = 0.f;
        else if (s == 0)   v = Wih3[rG*257];
        else if (s < 258)  v = Wih3[rG*257 + (s - 1)];
        else               v = Whh3[rG*Hdim + (s - 258)];
        w3p[idx] = v;
    }
    if (tid < 16) {
        int r = tid;
        int rG = ((r >> 2) << 7) + nt*UT + (r & 3);
        bsh[0*16 + r] = bih1[rG] + bhh1[rG];
        bsh[1*16 + r] = bih2[rG] + bhh2[rG];
        bsh[2*16 + r] = bih3[rG] + bhh3[rG];
    }
    for (int s = tid; s < 388; s += NTHR)
        wls[s] = (s >= 386 || s == 1) ? 0.f : ((s == 0) ? Wlin[0] : Wlin[s - 1]);
    if (tid == 0) sm[OFF_BL] = blin[0];
    for (int idx = tid; idx < 32*ASTR; idx += NTHR) ash[idx] = 0.f;   // h(-1)=0, pad=0
    for (int idx = tid; idx < 3*UT*32; idx += NTHR) csh[idx] = 0.f;

    const unsigned base = ld_acq(&g_flag[mt][0][nt][0]);   // replay-safe token base
    __syncthreads();

    const int Ttot = Tlen + fut;
    const int u = wi;        // cell-update mapping: warps 0..3, unit = wi, batch = lane
    const int m = lane;
    const float* arow = ash + lane*ASTR;
    const float blv = sm[OFF_BL];

    // per-warp k2 quarter bounds
    const int xlo = (K2_1*kq) >> 2, xhi = (K2_1*(kq+1)) >> 2;   // x+h1 [0,65)
    const int r2lo = K2_1 + 16*kq, r2hi = r2lo + 16;            // h2   [65,129)
    const int r3lo = K2_2 + 16*kq, r3hi = r3lo + 16;            // h3   [129,193)

    float xv = 0.f;
    if (tid < 32) xv = x[(m0 + tid)*Tlen + 0];

    for (int t = 0; t < Ttot; t++) {
        const unsigned tok0 = base + 3u*(unsigned)t + 1u;
        const unsigned tok1 = tok0 + 1u;
        const unsigned tok2 = tok0 + 2u;

        if (t < Tlen && tid < 32) ash[tid*ASTR] = xv;              // x slot
        if (tid < 32 && t + 1 < Tlen) xv = x[(m0 + tid)*Tlen + (t + 1)];
        __syncthreads();                                           // S0

        // ---------- layer 1 (x + h1(t-1): local) ----------
        {
            unsigned long long acc[8] = {0,0,0,0,0,0,0,0};
            gemm8(w1, arow, rg2, xlo, xhi, acc);
            store_gates8(gsh, kq, rg2, lane, acc);
        }
        __syncthreads();                                           // S1
        if (wi < 4) cell_update(0, u, m, nt, m0, gsh, bsh + 0, csh, &g_h[0][0][0]);
        __syncthreads();                                           // S2
        if (tid == 0) st_rel(&g_flag[mt][0][nt][0], tok0);

        // window0: recurrent partials on stale h2(t-1), h3(t-1) || wait h1(t)
        unsigned long long acc2[8] = {0,0,0,0,0,0,0,0};
        unsigned long long acc3[8] = {0,0,0,0,0,0,0,0};
        gemm8(w2p, arow, rg2, r2lo, r2hi, acc2);   // W_hh2 . h2(t-1)
        gemm8(w3p, arow, rg2, r3lo, r3hi, acc3);   // W_hh3 . h3(t-1)

        wait_refresh(mt, 0, tok0, wi, lane, &g_h[0][0][0], ash, 2, m0);    // h1(t) -> slots 2..129
        __syncthreads();                                           // S3

        // ---------- layer 2 finish (x + fresh h1) ----------
        gemm8(w2p, arow, rg2, xlo, xhi, acc2);
        store_gates8(gsh, kq, rg2, lane, acc2);
        __syncthreads();                                           // S4
        if (wi < 4) cell_update(1, u, m, nt, m0, gsh, bsh + 16, csh, &g_h[1][0][0]);
        __syncthreads();                                           // S5
        if (tid == 0) st_rel(&g_flag[mt][1][nt][0], tok1);

        // window1: layer3's x+h1 part || wait h2(t)
        gemm8(w3p, arow, rg2, xlo, xhi, acc3);

        wait_refresh(mt, 1, tok1, wi, lane, &g_h[1][0][0], ash, 130, m0);  // h2(t) -> slots 130..257
        __syncthreads();                                           // S6

        // ---------- layer 3 finish (fresh h2) ----------
        gemm8(w3p, arow, rg2, r2lo, r2hi, acc3);
        store_gates8(gsh, kq, rg2, lane, acc3);
        __syncthreads();                                           // S7
        if (wi < 4) cell_update(2, u, m, nt, m0, gsh, bsh + 32, csh, &g_h[2][0][0]);
        __syncthreads();                                           // S8
        if (tid == 0) st_rel(&g_flag[mt][2][nt][0], tok2);

        // window2: head partial over fresh x,h1,h2 || wait h3(t)
        const bool doo = (nt == 0) || (t >= Tlen - 1);
        float p = 0.f;
        if (doo) {   // slots [0,256): x, h1, h2 all fresh
            for (int k = wi; k < 256; k += 8) p = fmaf(wls[k], arow[k], p);
        }

        wait_refresh(mt, 2, tok2, wi, lane, &g_h[2][0][0], ash, 258, m0);  // h3(t) -> slots 258..385
        __syncthreads();                                           // S9

        if (doo) {
            for (int k = 256 + wi; k < 386; k += 8) p = fmaf(wls[k], arow[k], p);
            ops[wi*32 + lane] = p;
            __syncthreads();                                       // S10
            if (wi == 0) {
                float o = blv;
#pragma unroll
                for (int j = 0; j < 8; j++) o += ops[j*32 + lane];
                if (nt == 0) out[(m0 + lane)*Ttot + t] = o;
                if (t >= Tlen - 1) ash[lane*ASTR] = o;             // feed back as next x
            }
        }
        // loop-top __syncthreads (S0) orders feedback/refresh before next step's reads
    }
}

extern "C" void kernel_launch(void* const* d_in, const int* in_sizes, int n_in,
                              void* d_out, int out_size)
{
    const float* x    = (const float*)d_in[0];
    const float* Wih1 = (const float*)d_in[1];
    const float* Whh1 = (const float*)d_in[2];
    const float* bih1 = (const float*)d_in[3];
    const float* bhh1 = (const float*)d_in[4];
    const float* Wih2 = (const float*)d_in[5];
    const float* Whh2 = (const float*)d_in[6];
    const float* bih2 = (const float*)d_in[7];
    const float* bhh2 = (const float*)d_in[8];
    const float* Wih3 = (const float*)d_in[9];
    const float* Whh3 = (const float*)d_in[10];
    const float* bih3 = (const float*)d_in[11];
    const float* bhh3 = (const float*)d_in[12];
    const float* Wlin = (const float*)d_in[13];
    const float* blin = (const float*)d_in[14];
    (void)in_sizes; (void)n_in;

    int fut = out_size / Bsz - Tlen;

    cudaFuncSetAttribute((const void*)lstm_forecast_kernel,
                         cudaFuncAttributeMaxDynamicSharedMemorySize, SMEM_BYTES);

    lstm_forecast_kernel<<<NBLK, NTHR, SMEM_BYTES>>>(
        x, Wih1, Whh1, bih1, bhh1, Wih2, Whh2, bih2, bhh2,
        Wih3, Whh3, bih3, bhh3, Wlin, blin, (float*)d_out, fut);
}